// round 17
// baseline (speedup 1.0000x reference)
#include <cuda_runtime.h>
#include <cuda_bf16.h>

// VectorQuantizer forward, single fused kernel — final shape probe: TPB=512.
//   q    = codebook[categories]   (row gather, 512x768 codebook -> L2 resident)
//   out  = q
//   loss = 1.25 * mean((q - inputs)^2)
//
// Loss reduction: one packed 64-bit integer atomicAdd per block.
//   bits [0:50)  : fixed-point (2^20) partial sum (max ~1.05e14 < 2^50)
//   bits [50:64) : block-arrival count (14 bits >= 4096 blocks)
// Integer adds are associative -> bit-deterministic; the atomicAdd return
// value lets the last block detect completion AND recover the full sum.
//
// Shape grid status (GB300, R3-R16, all measured):
//  - TPB=256/ROWS=8: best total 65.6us (kernel 60.4, DRAM 73.9%).
//  - TPB=512/ROWS=16 (this probe): 4 blk/SM x 16 warps = 64/64 warps, regs 32;
//    half the epilogues/atomics per byte, wider store window.
//  - Persistent grid: straggler tail, 72.4us. Hints/fence: harmful.
//  - DRAM pinned 73-75% across all shapes = interleaved HBM3e r/w ceiling;
//    384MB payload irreducible.
//
// inputs:     [65536, 768] f32
// categories: [65536]      int32
// codebook:   [512, 768]   f32
// out:        65536*768 f32 quantized_st, then 1 f32 loss (if out_size permits)

#define VQ_BS    65536
#define VQ_D4    192                  // float4s per row
#define VQ_ROWS  16                   // rows per block
#define VQ_TPB   512                  // threads per block
#define VQ_F4PB  (VQ_ROWS * VQ_D4)    // 3072 float4s per block
#define VQ_ITERS (VQ_F4PB / VQ_TPB)   // 6 per thread
#define VQ_NBLK  (VQ_BS / VQ_ROWS)    // 4096 blocks
#define VQ_NWARP (VQ_TPB / 32)        // 16 warps

#define VQ_CNT_SHIFT 50
#define VQ_FX_SCALE  1048576.0        // 2^20

__device__ unsigned long long g_vq_acc = 0ULL;   // reset by last block -> replay-idempotent

__global__ __launch_bounds__(VQ_TPB, 4) void vq_kernel(
    const float4* __restrict__ in,
    const int* __restrict__ cat,
    const float4* __restrict__ cb,
    float4* __restrict__ out,
    float* __restrict__ loss_out,
    int write_loss)
{
    const int t = threadIdx.x;                       // 0..511
    const int row_base = blockIdx.x * VQ_ROWS;
    const size_t blk_f4 = (size_t)blockIdx.x * VQ_F4PB;

    // Hoist index gather once per block.
    __shared__ int scat[VQ_ROWS];
    if (t < VQ_ROWS) scat[t] = cat[row_base + t] & 511;   // mask: no-op on valid data
    __syncthreads();

    float s = 0.0f;

    #pragma unroll 3
    for (int k = 0; k < VQ_ITERS; k++) {
        const int idx = t + k * VQ_TPB;              // 0..3071 within block tile
        const int row = idx / VQ_D4;                 // const-div -> mul/shift
        const int col = idx - row * VQ_D4;
        const size_t gib = blk_f4 + idx;             // flat, fully coalesced
        float4 a = in[gib];
        float4 q = cb[(size_t)scat[row] * VQ_D4 + col];
        out[gib] = q;
        float dx = q.x - a.x;
        float dy = q.y - a.y;
        float dz = q.z - a.z;
        float dw = q.w - a.w;
        s += dx*dx + dy*dy + dz*dz + dw*dw;
    }

    // block reduction: 16 warps of 32
    #pragma unroll
    for (int o = 16; o > 0; o >>= 1)
        s += __shfl_down_sync(0xffffffffu, s, o);

    __shared__ float ws[VQ_NWARP];
    if ((t & 31) == 0) ws[t >> 5] = s;
    __syncthreads();

    if (t == 0) {
        float tot = 0.0f;
        #pragma unroll
        for (int w = 0; w < VQ_NWARP; w++) tot += ws[w];
        // fixed-point: ~2.4e4 per block -> ~2.5e10 scaled; total ~1.05e14 < 2^50
        unsigned long long fx = (unsigned long long)((double)tot * VQ_FX_SCALE);
        unsigned long long packed = (1ULL << VQ_CNT_SHIFT) + fx;
        unsigned long long old = atomicAdd(&g_vq_acc, packed);

        if ((old >> VQ_CNT_SHIFT) == (unsigned long long)(VQ_NBLK - 1)) {
            unsigned long long full = (old + packed) & ((1ULL << VQ_CNT_SHIFT) - 1ULL);
            if (write_loss) {
                const double inv_n = 1.0 / ((double)VQ_BS * 768.0);
                double mse = ((double)full / VQ_FX_SCALE) * inv_n;
                // loss = (CODEBOOK_COST + COMMITMENT_COST) * mse = 1.25 * mse
                loss_out[(size_t)VQ_BS * 768] = (float)(1.25 * mse);
            }
            g_vq_acc = 0ULL;   // reset for next graph replay (no other block alive)
        }
    }
}

extern "C" void kernel_launch(void* const* d_in, const int* in_sizes, int n_in,
                              void* d_out, int out_size)
{
    const float4* in  = (const float4*)d_in[0];
    const int*    cat = (const int*)d_in[1];
    const float4* cb  = (const float4*)d_in[2];
    float*        out = (float*)d_out;

    const int write_loss = (out_size > VQ_BS * 768) ? 1 : 0;
    vq_kernel<<<VQ_NBLK, VQ_TPB>>>(in, cat, cb, (float4*)out, out, write_loss);
}